// round 5
// baseline (speedup 1.0000x reference)
#include <cuda_runtime.h>

// x: [32, 28, 28, 512] fp32 (only batch 0 used); out: [32, 29, 29, 1] fp32.
#define HH    28
#define WW    28
#define CC    512
#define NPOS  (HH * WW)      // 784
#define OD    29
#define OUT2D (OD * OD)      // 841
#define BATCH 32
#define NCTA  49             // 16 warps/CTA * 49 = 784 positions
#define NTHREADS 512

// Separate cache lines: arrival counter, release flag, exit counter.
__device__ __align__(128) unsigned int g_count   = 0;
__device__ __align__(128) unsigned int g_release = 0;
__device__ __align__(128) unsigned int g_done    = 0;
__device__ __align__(128) float        g_fsq[NPOS];

__global__ void __launch_bounds__(NTHREADS)
fused_kernel(const float* __restrict__ x, float* __restrict__ out) {
    const int tid  = threadIdx.x;
    const int wid  = tid >> 5;
    const int lane = tid & 31;
    const int p    = blockIdx.x * 16 + wid;   // one warp per spatial position

    // ---------------- Phase 1: fsq[p] = sum_c x[0,p,c]^2 ----------------
    {
        const float4* xp = reinterpret_cast<const float4*>(x + (size_t)p * CC);
        float s = 0.f;
        #pragma unroll
        for (int k = 0; k < 4; ++k) {         // 4 independent float4 loads (MLP=4)
            const float4 v = xp[k * 32 + lane];
            s += v.x * v.x + v.y * v.y + v.z * v.z + v.w * v.w;
        }
        #pragma unroll
        for (int o = 16; o > 0; o >>= 1)
            s += __shfl_xor_sync(0xffffffffu, s, o);
        if (lane == 0)
            g_fsq[p] = s;
    }
    __syncthreads();                          // all 16 g_fsq stores of this CTA issued

    // Arrival: one atomic per CTA; the 49th arriver publishes the release flag
    // on a DIFFERENT cache line so spinner polls never contend with arrivals.
    if (tid == 0) {
        __threadfence();                       // release this CTA's g_fsq writes
        const unsigned int old = atomicAdd(&g_count, 1u);
        if (old == (unsigned int)(NCTA - 1)) { // all 49 fenced writes now visible
            __threadfence();
            *(volatile unsigned int*)&g_release = 1u;
        }
    }

    if (blockIdx.x >= BATCH) return;           // 17 CTAs done (after arriving)

    // ---------------- Phase 2: CTAs 0..31, one batch element each ----------
    const int b = blockIdx.x;

    __shared__ unsigned int done_s;
    if (tid == 0) {
        // All 49 CTAs co-resident -> spin cannot deadlock. Poll read-only flag.
        volatile unsigned int* vf = &g_release;
        while (*vf == 0u) { }
        done_s = atomicAdd(&g_done, 1u);       // record spin-exit for reset election
    }
    __syncthreads();
    __threadfence();                           // acquire g_fsq

    __shared__ float fsq_s[NPOS];
    __shared__ float I[OD][OD + 3];            // pad vs bank conflicts

    #pragma unroll
    for (int k = tid; k < NPOS; k += NTHREADS)
        fsq_s[k] = __ldcg(&g_fsq[k]);

    if (tid < OD) { I[tid][0] = 0.f; I[0][tid] = 0.f; }

    // Last spin-exiter resets counters for the next graph replay (all spinners
    // are already past the flag; nobody reads these again this launch).
    if (tid == 0 && done_s == (unsigned int)(BATCH - 1)) {
        *(volatile unsigned int*)&g_release = 0u;
        g_count = 0u;
        g_done  = 0u;
    }
    __syncthreads();

    // Row cumsums (28 threads, register FADD chain).
    if (tid < HH) {
        float run = 0.f;
        #pragma unroll
        for (int c = 0; c < WW; ++c) {
            run += fsq_s[tid * WW + c];
            I[tid + 1][c + 1] = run;
        }
    }
    __syncthreads();

    // Column cumsums (28 threads).
    if (tid < WW) {
        const int c = tid + 1;
        float run = 0.f;
        #pragma unroll
        for (int r = 1; r <= HH; ++r) {
            run += I[r][c];
            I[r][c] = run;
        }
    }
    __syncthreads();

    // Box sums -> this block's batch slice (2 iterations per thread).
    float* ob = out + (size_t)b * OUT2D;
    #pragma unroll
    for (int k = tid; k < OUT2D; k += NTHREADS) {
        const int i = k / OD, j = k - i * OD;
        const int r0 = min(max(HH / 2 - i, 0), HH);
        const int r1 = min(max(HH / 2 + HH - i, 0), HH);
        const int c0 = min(max(WW / 2 - j, 0), WW);
        const int c1 = min(max(WW / 2 + WW - j, 0), WW);
        ob[k] = I[r1][c1] - I[r0][c1] - I[r1][c0] + I[r0][c0];
    }
}

extern "C" void kernel_launch(void* const* d_in, const int* in_sizes, int n_in,
                              void* d_out, int out_size) {
    const float* x = (const float*)d_in[0];
    float* out     = (float*)d_out;
    fused_kernel<<<NCTA, NTHREADS>>>(x, out);
}

// round 6
// speedup vs baseline: 1.2362x; 1.2362x over previous
#include <cuda_runtime.h>

// x: [32, 28, 28, 512] fp32 (only batch 0 used); out: [32, 29, 29, 1] fp32.
#define HH    28
#define WW    28
#define CC    512
#define NPOS  (HH * WW)      // 784
#define OD    29
#define PITCH 33             // odd pitch -> conflict-free column writes
#define OUT2D (OD * OD)      // 841
#define BATCH 32
#define NCTA  49             // 16 warps/CTA * 49 = 784 positions
#define NTHREADS 512

struct __align__(128) PaddedFlag { unsigned int v; unsigned int pad[31]; };

__device__ PaddedFlag   g_flag[NCTA];          // zero-initialized
__device__ __align__(128) unsigned int g_done = 0;
__device__ __align__(128) float g_fsq[NPOS];

__global__ void __launch_bounds__(NTHREADS)
fused_kernel(const float* __restrict__ x, float* __restrict__ out) {
    const int tid  = threadIdx.x;
    const int wid  = tid >> 5;
    const int lane = tid & 31;
    const int p    = blockIdx.x * 16 + wid;    // one warp per spatial position

    // ---------------- Phase 1: fsq[p] = sum_c x[0,p,c]^2 ----------------
    {
        const float4* xp = reinterpret_cast<const float4*>(x + (size_t)p * CC);
        float s = 0.f;
        #pragma unroll
        for (int k = 0; k < 4; ++k) {
            const float4 v = xp[k * 32 + lane];
            s += v.x * v.x + v.y * v.y + v.z * v.z + v.w * v.w;
        }
        #pragma unroll
        for (int o = 16; o > 0; o >>= 1)
            s += __shfl_xor_sync(0xffffffffu, s, o);
        if (lane == 0)
            g_fsq[p] = s;
    }
    __syncthreads();                           // CTA's 16 g_fsq stores ordered to tid0

    // Arrival: parallel per-CTA flag stores (no atomic chain, no aggregator hop).
    if (tid == 0) {
        __threadfence();                       // release g_fsq (block stores HB via bar)
        *(volatile unsigned int*)&g_flag[blockIdx.x].v = 1u;
    }

    if (blockIdx.x >= BATCH) return;           // 17 CTAs done

    // ---------------- Phase 2: CTAs 0..31, one batch element each ----------
    const int b = blockIdx.x;

    __shared__ float I[OD][PITCH];
    __shared__ unsigned int done_s;

    // Borders: independent of data, do before the spin.
    if (tid < OD) { I[tid][0] = 0.f; I[0][tid] = 0.f; }

    // Each of 49 threads polls one distinct flag; all in parallel.
    if (tid < NCTA) {
        volatile unsigned int* vf = &g_flag[tid].v;
        while (*vf == 0u) { }
    }
    __syncthreads();                           // join: all 49 flags seen set
    __threadfence();                           // acquire g_fsq

    // Election for reset: AFTER full join, so reset can never race a spinner.
    if (tid == 0)
        done_s = atomicAdd(&g_done, 1u);

    // Row cumsums: thread r loads its row straight from L2 (7x float4, rows
    // are 112B and 16B-aligned) and writes the running sum. PITCH=33 ->
    // stores across threads are conflict-free.
    if (tid < HH) {
        const float4* row = reinterpret_cast<const float4*>(g_fsq + tid * WW);
        float run = 0.f;
        #pragma unroll
        for (int q = 0; q < 7; ++q) {
            const float4 v = __ldcg(&row[q]);
            run += v.x; I[tid + 1][q * 4 + 1] = run;
            run += v.y; I[tid + 1][q * 4 + 2] = run;
            run += v.z; I[tid + 1][q * 4 + 3] = run;
            run += v.w; I[tid + 1][q * 4 + 4] = run;
        }
    }
    __syncthreads();

    // Column cumsums (threads access consecutive columns: conflict-free).
    if (tid < WW) {
        const int c = tid + 1;
        float run = 0.f;
        #pragma unroll
        for (int r = 1; r <= HH; ++r) {
            run += I[r][c];
            I[r][c] = run;
        }
    }
    __syncthreads();

    // Last-joined CTA resets flags + counter (all 32 tails already joined).
    if (done_s == (unsigned int)(BATCH - 1)) {
        if (tid < NCTA) *(volatile unsigned int*)&g_flag[tid].v = 0u;
        if (tid == 0)   atomicExch(&g_done, 0u);
    }

    // Box sums -> this block's batch slice (2 iterations per thread).
    float* ob = out + (size_t)b * OUT2D;
    #pragma unroll
    for (int k = tid; k < OUT2D; k += NTHREADS) {
        const int i = k / OD, j = k - i * OD;
        const int r0 = min(max(HH / 2 - i, 0), HH);
        const int r1 = min(max(HH / 2 + HH - i, 0), HH);
        const int c0 = min(max(WW / 2 - j, 0), WW);
        const int c1 = min(max(WW / 2 + WW - j, 0), WW);
        ob[k] = I[r1][c1] - I[r0][c1] - I[r1][c0] + I[r0][c0];
    }
}

extern "C" void kernel_launch(void* const* d_in, const int* in_sizes, int n_in,
                              void* d_out, int out_size) {
    const float* x = (const float*)d_in[0];
    float* out     = (float*)d_out;
    fused_kernel<<<NCTA, NTHREADS>>>(x, out);
}